// round 11
// baseline (speedup 1.0000x reference)
#include <cuda_runtime.h>
#include <cstddef>

// ---------------- problem constants ----------------
#define H       512
#define IDIM    128
#define KIN     640          // H + I
#define SEQ     256
#define OUTLEN  64
#define CDIM    64
#define BATCH   32
#define NSTEPS  (SEQ + OUTLEN)

// ---------------- partition: 128 CTAs = 2 chains x 64 col-CTAs ----------------
#define GROUPS  2
#define PCOLS   64
#define BG      (BATCH / GROUPS)   // 16 rows per chain
#define COLS    8                  // hidden cols per CTA
#define NCTAS   (GROUPS * PCOLS)   // 128
#define TPB     256
#define RINGD   32                 // ring depth (power of two >= 17)

#define SW      644                // KIN + 4, col stride in sWall

// ---------------- SMEM layout (floats) ----------------
#define OFF_WALL  0                         // 48 cols x 644 = 30912
#define OFF_WOUT  30912                     // 516
#define OFF_BIAS  31428                     // 64: sbin@0 sbp@8 sbtA@16 sbtB@24 sbmA@32 sbmB@40 sbout@48
#define OFF_SLEN  31492                     // 16 ints
#define OFF_CHS   31508                     // 16 rows x 640 = 10240
#define OFF_TMP   41748                     // 16 x 49 = 784
#define OFF_SCR   42532                     // 256
#define OFF_BPF   42788                     // 512 (bpfull)
#define OFF_RING  43300                     // 32 x 128 = 4096
#define SMEM_FLOATS 47396
#define SMEM_BYTES  (SMEM_FLOATS * 4)       // 189,584 B

typedef unsigned long long ull;

// ---------------- global staging / scratch / flags ----------------
__device__ __align__(16) float g_h0[2][GROUPS][BG * H];     // double-buffered
__device__ __align__(16) float g_PT[H * H];                 // W_pass@W_tau
__device__ __align__(16) float g_PM[H * H];                 // W_pass@W_mem
// 5 fused matrices, [mat][col][k] transposed: 0=Wf 1=WtA 2=WtB 3=WmA 4=WmB
__device__ __align__(16) float g_fw[5 * H * KIN];

__device__ unsigned g_flg[GROUPS * PCOLS * 32];             // 128B-padded flags

struct __align__(128) AllBar { unsigned count; unsigned sense; unsigned pad[30]; };
__device__ AllBar g_allbar;

__device__ __forceinline__ float sigf(float z) { return 1.f / (1.f + __expf(-z)); }

__device__ __forceinline__ void st_rel(unsigned* a, unsigned v) {
    asm volatile("st.release.gpu.global.u32 [%0], %1;" :: "l"(a), "r"(v) : "memory");
}
__device__ __forceinline__ unsigned ld_acq(const unsigned* a) {
    unsigned v;
    asm volatile("ld.acquire.gpu.global.u32 %0, [%1];" : "=r"(v) : "l"(a) : "memory");
    return v;
}

#define PUBLISH(val)                                                           \
    do {                                                                       \
        __syncthreads();                                                       \
        if (tid == 0) st_rel(&g_flg[(g * PCOLS + p) * 32], (unsigned)(val));   \
    } while (0)

#define WAIT_FLAGS(val)                                                        \
    do {                                                                       \
        if (tid < PCOLS) {                                                     \
            const unsigned* fp = &g_flg[(g * PCOLS + tid) * 32];               \
            while (ld_acq(fp) < (unsigned)(val)) { }                           \
        }                                                                      \
        __syncthreads();                                                       \
    } while (0)

// packed dual-FMA: acc(2xf32) += h(2xf32) * w(2xf32)
__device__ __forceinline__ void fma2pk(ull& acc, double h, double w)
{
    asm("fma.rn.f32x2 %0, %1, %2, %0;"
        : "+l"(acc)
        : "l"(__double_as_longlong(h)), "l"(__double_as_longlong(w)));
}
__device__ __forceinline__ float pk_sum(ull a)
{
    float lo = __uint_as_float((unsigned)(a & 0xffffffffu));
    float hi = __uint_as_float((unsigned)(a >> 32));
    return lo + hi;
}

extern "C" __global__ void __launch_bounds__(TPB, 1)
delay_rnn_kernel(const float* __restrict__ x,       // [B, S, I]
                 const int*   __restrict__ lengths, // [B]
                 const float* __restrict__ W_in,    // [KIN, H]
                 const float* __restrict__ b_in,
                 const float* __restrict__ W_pass,  // [H, H]
                 const float* __restrict__ b_pass,
                 const float* __restrict__ W_tau,
                 const float* __restrict__ b_tau,
                 const float* __restrict__ W_mem,
                 const float* __restrict__ b_mem,
                 const float* __restrict__ W_out,   // [H, C]
                 const float* __restrict__ b_out,
                 float*       __restrict__ out)     // [B, OUTLEN, C]
{
    extern __shared__ float sm[];
    const int tid     = threadIdx.x;
    const int cta     = blockIdx.x;
    const int g       = cta >> 6;        // chain id (0/1)
    const int p       = cta & 63;        // column partition (0..63)
    const int b0      = g * BG;
    const int colbase = p * COLS;        // 8 cols per CTA
    const int c4      = cta * 4;         // 4 global cols this CTA builds in prologue

    float* sWall = sm + OFF_WALL;        // 48 cols x SW
    float* sWout = sm + OFF_WOUT;
    float* sbin  = sm + OFF_BIAS;        // 8
    float* sbp   = sbin + 8;
    float* sbtA  = sbin + 16;
    float* sbtB  = sbin + 24;
    float* sbmA  = sbin + 32;
    float* sbmB  = sbin + 40;
    float* sbout = sbin + 48;            // 1 used
    int*   slen  = (int*)(sm + OFF_SLEN);
    float* chs   = sm + OFF_CHS;         // 16 rows x 640
    float* tmp   = sm + OFF_TMP;         // 16 x 49
    float* scr   = sm + OFF_SCR;         // 256
    float* bpf   = sm + OFF_BPF;         // 512
    float* ring  = sm + OFF_RING;        // 32 x 128

    unsigned bsense = 0;
    if (tid == 0) bsense = *(volatile unsigned*)&g_allbar.sense;

    auto ALLBAR = [&]() {
        __threadfence();
        __syncthreads();
        if (tid == 0) {
            unsigned ns = bsense ^ 1u;
            bsense = ns;
            if (atomicAdd(&g_allbar.count, 1u) == (unsigned)(NCTAS - 1)) {
                g_allbar.count = 0u;
                __threadfence();
                atomicExch(&g_allbar.sense, ns);
            } else {
                while (*(volatile unsigned*)&g_allbar.sense != ns) { }
            }
        }
        __syncthreads();
    };

    // ================= prologue =================
    // ring zero + initial h0 (buffer 0) zero, publish epoch 1
    for (int idx = tid; idx < RINGD * 128; idx += TPB) ring[idx] = 0.f;
    if (tid < 128) {
        int row = tid >> 3, cl = tid & 7;
        g_h0[0][g][row * H + colbase + cl] = 0.f;
    }
    PUBLISH(1);

    // ---- stage 1: PT = W_pass@W_tau, PM = W_pass@W_mem (4 cols each per CTA) ----
    for (int idx = tid; idx < 8 * H; idx += TPB) {
        int i = idx >> 9, j = idx & 511;
        chs[i * H + j] = (i < 4) ? W_tau[j * H + c4 + i]
                                 : W_mem[j * H + c4 + (i - 4)];
    }
    __syncthreads();
    for (int j = tid; j < H; j += TPB) {
        float a[8] = {0.f, 0.f, 0.f, 0.f, 0.f, 0.f, 0.f, 0.f};
        const float* wr = W_pass + (size_t)j * H;
        for (int kk = 0; kk < H; kk += 4) {
            float4 w4 = __ldg((const float4*)(wr + kk));
#pragma unroll
            for (int i = 0; i < 8; ++i) {
                const float* cc = chs + i * H + kk;
                a[i] = fmaf(w4.x, cc[0], a[i]); a[i] = fmaf(w4.y, cc[1], a[i]);
                a[i] = fmaf(w4.z, cc[2], a[i]); a[i] = fmaf(w4.w, cc[3], a[i]);
            }
        }
#pragma unroll
        for (int i = 0; i < 4; ++i) g_PT[j * H + c4 + i] = a[i];
#pragma unroll
        for (int i = 0; i < 4; ++i) g_PM[j * H + c4 + i] = a[4 + i];
    }
    ALLBAR();

    // ---- stage 2: five fused matrices, 4 cols each per CTA ----
    // sources: m=0 Wpass(->Wf), 1 PT(->WtA), 2 Wtau(->WtB), 3 PM(->WmA), 4 Wmem(->WmB)
    for (int idx = tid; idx < 20 * H; idx += TPB) {
        int mi = idx >> 9, j = idx & 511;
        int m = mi >> 2, i = mi & 3;
        float v;
        if      (m == 0) v = W_pass[j * H + c4 + i];
        else if (m == 1) v = g_PT  [j * H + c4 + i];
        else if (m == 2) v = W_tau [j * H + c4 + i];
        else if (m == 3) v = g_PM  [j * H + c4 + i];
        else             v = W_mem [j * H + c4 + i];
        chs[mi * H + j] = v;
    }
    __syncthreads();
    for (int k = tid; k < KIN; k += TPB) {
        float a[20];
#pragma unroll
        for (int i = 0; i < 20; ++i) a[i] = 0.f;
        const float* wr = W_in + (size_t)k * H;
        for (int kk = 0; kk < H; kk += 4) {
            float4 w4 = __ldg((const float4*)(wr + kk));
#pragma unroll
            for (int mi = 0; mi < 20; ++mi) {
                const float* cc = chs + mi * H + kk;
                a[mi] = fmaf(w4.x, cc[0], a[mi]); a[mi] = fmaf(w4.y, cc[1], a[mi]);
                a[mi] = fmaf(w4.z, cc[2], a[mi]); a[mi] = fmaf(w4.w, cc[3], a[mi]);
            }
        }
#pragma unroll
        for (int mi = 0; mi < 20; ++mi) {
            int m = mi >> 2, i = mi & 3;
            g_fw[((size_t)m * H + c4 + i) * KIN + k] = a[mi];
        }
    }
    __syncthreads();

    // ---- bias constants (independent of g_fw) ----
    // bpfull = b_in@W_pass + b_pass
    for (int c = tid; c < H; c += TPB) {
        float a = b_pass[c];
        for (int j = 0; j < H; ++j) a = fmaf(b_in[j], W_pass[j * H + c], a);
        bpf[c] = a;
    }
    __syncthreads();
    {   // btA/btB/bmA/bmB for own 8 cols: 32 splits of 16 each, partials in chs
        int cl = tid & 7, s = tid >> 3;          // 256 threads = 8 cols x 32 splits
        int gc = colbase + cl;
        float a1 = 0.f, a2 = 0.f, a3 = 0.f, a4 = 0.f;
        for (int j = s * 16; j < s * 16 + 16; ++j) {
            float wt = W_tau[j * H + gc], wm = W_mem[j * H + gc];
            a1 = fmaf(bpf[j],  wt, a1);
            a2 = fmaf(b_in[j], wt, a2);
            a3 = fmaf(bpf[j],  wm, a3);
            a4 = fmaf(b_in[j], wm, a4);
        }
        chs[tid] = a1; chs[256 + tid] = a2; chs[512 + tid] = a3; chs[768 + tid] = a4;
    }
    __syncthreads();
    if (tid < 8) {
        int gc = colbase + tid;
        float r1 = b_tau[gc], r2 = b_tau[gc], r3 = b_mem[gc], r4 = b_mem[gc];
        for (int s = 0; s < 32; ++s) {
            r1 += chs[s * 8 + tid];
            r2 += chs[256 + s * 8 + tid];
            r3 += chs[512 + s * 8 + tid];
            r4 += chs[768 + s * 8 + tid];
        }
        sbtA[tid] = r1; sbtB[tid] = r2; sbmA[tid] = r3; sbmB[tid] = r4;
        sbin[tid] = b_in[gc];
        sbp[tid]  = bpf[gc];
    }
    if (tid == 0) sbout[0] = b_out[p];
    if (tid < BG) slen[tid] = lengths[b0 + tid];

    ALLBAR();   // g_fw fully visible

    // ---- SMEM weight loads ----
    // mat 0 = W_in (transpose from input)
    for (int idx = tid; idx < KIN * 8; idx += TPB) {
        int k = idx >> 3, cl = idx & 7;
        sWall[cl * SW + k] = W_in[(size_t)k * H + colbase + cl];
    }
    // mats 1..5 from g_fw (contiguous in k -> float4)
    for (int idx = tid; idx < 5 * 8 * (KIN / 4); idx += TPB) {
        int m  = idx / (8 * (KIN / 4));
        int r  = idx - m * (8 * (KIN / 4));
        int cl = r / (KIN / 4);
        int q  = r - cl * (KIN / 4);
        float4 v = *((const float4*)(g_fw + ((size_t)m * H + colbase + cl) * KIN) + q);
        *((float4*)(sWall + ((m + 1) * 8 + cl) * SW) + q) = v;
    }
    // W_out column p
    for (int idx = tid; idx < H; idx += TPB) sWout[idx] = W_out[(size_t)idx * CDIM + p];
    __syncthreads();

    const int wid  = tid >> 5;
    const int lane = tid & 31;

    // ================= main loop: ONE exchange per step =================
    for (int st = 0; st < NSTEPS; ++st) {
        const bool enc = (st < SEQ);
        const int  nj  = enc ? 5 : 4;

        // x_t prefetch before the wait (independent data)
        if (enc) {
            for (int idx = tid; idx < 512; idx += TPB) {   // 16 rows x 32 f4
                int row = idx >> 5, iq = idx & 31;
                float4 v = __ldg((const float4*)(x + ((size_t)(b0 + row) * SEQ + st) * IDIM) + iq);
                *((float4*)(chs + row * KIN + H) + iq) = v;
            }
        }
        WAIT_FLAGS(st + 1);

        // gather h0 (16 x 512) from current buffer
        {
            const float4* src = (const float4*)g_h0[st & 1][g];
            for (int idx = tid; idx < (BG * H) / 4; idx += TPB) {
                int row = idx >> 7, kq = idx & 127;
                *((float4*)(chs + row * KIN) + kq) = __ldcg(src + idx);
            }
        }
        __syncthreads();

        // GEMM: 16 rows x 48 cols, 3 passes x 8 warps, tile 8x4, lane = 32-way split-K
#pragma unroll
        for (int pass = 0; pass < 3; ++pass) {
            const int t  = pass * 8 + wid;
            const int rg = t & 1;                 // row group (8 rows)
            const int cg = t >> 1;                // col group (4 cols), 0..11
            ull acc[8][4];
#pragma unroll
            for (int r = 0; r < 8; ++r)
#pragma unroll
                for (int c = 0; c < 4; ++c) acc[r][c] = 0ull;

#pragma unroll 5
            for (int j = 0; j < nj; ++j) {
                const int k = lane * 4 + j * 128;
                double2 hd[8], wd[4];
#pragma unroll
                for (int r = 0; r < 8; ++r)
                    hd[r] = *(const double2*)(chs + (rg * 8 + r) * KIN + k);
#pragma unroll
                for (int c = 0; c < 4; ++c)
                    wd[c] = *(const double2*)(sWall + (cg * 4 + c) * SW + k);
#pragma unroll
                for (int r = 0; r < 8; ++r)
#pragma unroll
                    for (int c = 0; c < 4; ++c) {
                        fma2pk(acc[r][c], hd[r].x, wd[c].x);
                        fma2pk(acc[r][c], hd[r].y, wd[c].y);
                    }
            }

            // butterfly reduce 32 outputs across 32 lanes -> lane owns output idx == lane
            float f[32];
#pragma unroll
            for (int r = 0; r < 8; ++r)
#pragma unroll
                for (int c = 0; c < 4; ++c) f[r * 4 + c] = pk_sum(acc[r][c]);
#pragma unroll
            for (int m = 16; m >= 1; m >>= 1) {
                bool up = (lane & m) != 0;
#pragma unroll
                for (int i = 0; i < m; ++i) {
                    float send = up ? f[i] : f[i + m];
                    float recv = __shfl_xor_sync(0xffffffffu, send, m);
                    f[i] = (up ? f[i + m] : f[i]) + recv;
                }
            }
            tmp[(rg * 8 + (lane >> 2)) * 49 + cg * 4 + (lane & 3)] = f[0];
        }
        __syncthreads();

        // epilogue: gates + mix + ring update, one thread per (row, col) entry
        if (tid < 128) {
            const int row = tid >> 3, cl = tid & 7;
            const float* tr = tmp + row * 49;
            float hpre = tr[cl]      + sbin[cl];
            float pv   = tr[8 + cl]  + sbp[cl];
            float tA   = tr[16 + cl] + sbtA[cl];
            float tB   = tr[24 + cl] + sbtB[cl];
            float mA   = tr[32 + cl] + sbmA[cl];
            float mB   = tr[40 + cl] + sbmB[cl];
            const bool msel = (!enc) || (st < slen[row]);
            float hv  = msel ? pv : hpre;
            float tau = fminf(fmaxf(16.f * sigf(msel ? tA : tB), 1.f), 16.f);
            float ml  = sigf(msel ? mA : mB);

            ring[(st & (RINGD - 1)) * 128 + tid] = 0.f;    // retire consumed slot
#pragma unroll
            for (int jp = 1; jp <= 16; ++jp) {
                const int slot = (st + jp) & (RINGD - 1);
                const float w = ml / (1.f + fabsf(tau - (float)jp));
                ring[slot * 128 + tid] += w * hv;
            }
            const float h0n = ring[((st + 1) & (RINGD - 1)) * 128 + tid];
            g_h0[(st + 1) & 1][g][row * H + colbase + cl] = h0n;
        }
        PUBLISH(st + 2);

        // decode output AFTER publish (chs h-region still holds h0(st))
        if (!enc) {
            const int row = tid >> 4, kp = tid & 15;       // 16 rows x 16 splits
            const float* hr = chs + row * KIN + kp * 32;
            const float* wr = sWout + kp * 32;
            float a = 0.f;
#pragma unroll
            for (int k = 0; k < 32; k += 4) {
                float4 h4 = *(const float4*)(hr + k);
                float4 w4 = *(const float4*)(wr + k);
                a = fmaf(h4.x, w4.x, a); a = fmaf(h4.y, w4.y, a);
                a = fmaf(h4.z, w4.z, a); a = fmaf(h4.w, w4.w, a);
            }
            scr[tid] = a;
            __syncthreads();
            if (tid < 16) {
                float s = sbout[0];
#pragma unroll
                for (int j2 = 0; j2 < 16; ++j2) s += scr[tid * 16 + j2];
                const int td = st - SEQ;
                out[((size_t)(b0 + tid) * OUTLEN + td) * CDIM + p] = s;
            }
            __syncthreads();   // protect scr/chs before next-step writes
        }
    }

    // drain all CTAs, then reset flags for the next graph replay
    ALLBAR();
    if (tid == 0) g_flg[(g * PCOLS + p) * 32] = 0u;
}

extern "C" void kernel_launch(void* const* d_in, const int* in_sizes, int n_in,
                              void* d_out, int out_size)
{
    int wi = 2;
    if (n_in > 2 && in_sizes[2] == 1) wi = 3;   // skip scalar out_lengths if present

    const float* x       = (const float*)d_in[0];
    const int*   lengths = (const int*)  d_in[1];
    const float* W_in    = (const float*)d_in[wi + 0];
    const float* b_in    = (const float*)d_in[wi + 1];
    const float* W_pass  = (const float*)d_in[wi + 2];
    const float* b_pass  = (const float*)d_in[wi + 3];
    const float* W_tau   = (const float*)d_in[wi + 4];
    const float* b_tau   = (const float*)d_in[wi + 5];
    const float* W_mem   = (const float*)d_in[wi + 6];
    const float* b_mem   = (const float*)d_in[wi + 7];
    const float* W_out   = (const float*)d_in[wi + 8];
    const float* b_out   = (const float*)d_in[wi + 9];

    cudaFuncSetAttribute(delay_rnn_kernel,
                         cudaFuncAttributeMaxDynamicSharedMemorySize, SMEM_BYTES);

    delay_rnn_kernel<<<NCTAS, TPB, SMEM_BYTES>>>(
        x, lengths, W_in, b_in, W_pass, b_pass, W_tau, b_tau,
        W_mem, b_mem, W_out, b_out, (float*)d_out);
}